// round 1
// baseline (speedup 1.0000x reference)
#include <cuda_runtime.h>
#include <math.h>

// Problem constants
#define NQ   32768      // N*S1*S2
#define CH   64
#define MOFF 27

// Halo tile: queries = 1(n) x 4(a) x 8(b); halo = 3 x 6 x 10
#define HN 3
#define HA 6
#define HB 10
#define HSZ (HN*HA*HB)          // 180
#define ATTN_SMEM ((HSZ*64 + 4096 + 4096) * 4)   // 78848 bytes

// Scratch (static device globals: allocation-free per harness rules)
__device__ float g_h0[NQ * CH];
__device__ float g_h1[NQ * CH];
__device__ float g_stats[8];    // mean[0..2], rsigma[4..6]

typedef unsigned long long ull;

__device__ __forceinline__ ull pack2(float x, float y) {
    ull r;
    asm("mov.b64 %0, {%1, %2};" : "=l"(r) : "r"(__float_as_uint(x)), "r"(__float_as_uint(y)));
    return r;
}
__device__ __forceinline__ ull splat2(float x) {
    ull r;
    asm("mov.b64 %0, {%1, %1};" : "=l"(r) : "r"(__float_as_uint(x)));
    return r;
}
__device__ __forceinline__ void unpack2(ull p, float& x, float& y) {
    unsigned lo, hi;
    asm("mov.b64 {%0, %1}, %2;" : "=r"(lo), "=r"(hi) : "l"(p));
    x = __uint_as_float(lo); y = __uint_as_float(hi);
}
// Packed dual FP32 FMA (Blackwell FFMA2) — 2x fp32 throughput
__device__ __forceinline__ ull ffma2(ull a, ull b, ull c) {
    ull d;
    asm("fma.rn.f32x2 %0, %1, %2, %3;" : "=l"(d) : "l"(a), "l"(b), "l"(c));
    return d;
}
__device__ __forceinline__ ull lds_u64(const float* p) {
    return *reinterpret_cast<const ull*>(p);
}

// ---------------------------------------------------------------------------
// 1) BatchNorm batch statistics over all 32768 positions, per feature (F=3)
// ---------------------------------------------------------------------------
__global__ void bn_stats_kernel(const float* __restrict__ x) {
    float s0 = 0.f, s1 = 0.f, s2 = 0.f, t0 = 0.f, t1 = 0.f, t2 = 0.f;
    for (int p = threadIdx.x; p < NQ; p += 1024) {
        float v0 = x[p * 3 + 0], v1 = x[p * 3 + 1], v2 = x[p * 3 + 2];
        s0 += v0; s1 += v1; s2 += v2;
        t0 += v0 * v0; t1 += v1 * v1; t2 += v2 * v2;
    }
#pragma unroll
    for (int o = 16; o; o >>= 1) {
        s0 += __shfl_xor_sync(0xffffffffu, s0, o);
        s1 += __shfl_xor_sync(0xffffffffu, s1, o);
        s2 += __shfl_xor_sync(0xffffffffu, s2, o);
        t0 += __shfl_xor_sync(0xffffffffu, t0, o);
        t1 += __shfl_xor_sync(0xffffffffu, t1, o);
        t2 += __shfl_xor_sync(0xffffffffu, t2, o);
    }
    __shared__ float red[32][6];
    int lane = threadIdx.x & 31, w = threadIdx.x >> 5;
    if (lane == 0) {
        red[w][0] = s0; red[w][1] = s1; red[w][2] = s2;
        red[w][3] = t0; red[w][4] = t1; red[w][5] = t2;
    }
    __syncthreads();
    if (threadIdx.x < 32) {
        float a0 = red[lane][0], a1 = red[lane][1], a2 = red[lane][2];
        float a3 = red[lane][3], a4 = red[lane][4], a5 = red[lane][5];
#pragma unroll
        for (int o = 16; o; o >>= 1) {
            a0 += __shfl_xor_sync(0xffffffffu, a0, o);
            a1 += __shfl_xor_sync(0xffffffffu, a1, o);
            a2 += __shfl_xor_sync(0xffffffffu, a2, o);
            a3 += __shfl_xor_sync(0xffffffffu, a3, o);
            a4 += __shfl_xor_sync(0xffffffffu, a4, o);
            a5 += __shfl_xor_sync(0xffffffffu, a5, o);
        }
        if (lane == 0) {
            const float inv = 1.0f / (float)NQ;
            float m0 = a0 * inv, m1 = a1 * inv, m2 = a2 * inv;
            g_stats[0] = m0; g_stats[1] = m1; g_stats[2] = m2;
            g_stats[4] = rsqrtf(a3 * inv - m0 * m0 + 1e-5f);
            g_stats[5] = rsqrtf(a4 * inv - m1 * m1 + 1e-5f);
            g_stats[6] = rsqrtf(a5 * inv - m2 * m2 + 1e-5f);
        }
    }
}

// ---------------------------------------------------------------------------
// 2) h0 = normalize(x) @ W_in + b_in     [NQ, 64]
// ---------------------------------------------------------------------------
__global__ void input_proj_kernel(const float* __restrict__ x,
                                  const float* __restrict__ W_in,
                                  const float* __restrict__ b_in,
                                  float* __restrict__ h_out) {
    int idx = blockIdx.x * 256 + threadIdx.x;     // NQ*64 threads
    int p = idx >> 6, c = idx & 63;
    float acc = b_in[c];
#pragma unroll
    for (int f = 0; f < 3; f++) {
        float xn = (x[p * 3 + f] - g_stats[f]) * g_stats[4 + f];
        acc += xn * W_in[f * CH + c];
    }
    h_out[idx] = acc;
}

// ---------------------------------------------------------------------------
// 3) Fused attention layer.
//    Block = 256 threads, 32 queries (1n x 4a x 8b tile).
//    warp qg handles queries 4*qg..4*qg+3; lane c2 handles channels 2c2,2c2+1.
//    Online softmax over the 27 offsets; weights staged per-offset in smem.
// ---------------------------------------------------------------------------
__global__ __launch_bounds__(256, 2)
void attn_kernel(const float* __restrict__ h_in, float* __restrict__ h_out,
                 const float* __restrict__ Wq, const float* __restrict__ bq,
                 const float* __restrict__ Wk, const float* __restrict__ bk,
                 const float* __restrict__ Wv, const float* __restrict__ bv) {
    extern __shared__ float smem[];
    float* h_s  = smem;                 // HSZ * 64
    float* wk_s = smem + HSZ * 64;      // 4096
    float* wv_s = wk_s + 4096;          // 4096

    const int tid = threadIdx.x;
    const int c2  = tid & 31;           // channel pair index
    const int qg  = tid >> 5;           // warp id

    const int bx = blockIdx.x;
    const int tn = bx >> 5;
    const int a0 = ((bx >> 2) & 7) << 2;
    const int b0 = (bx & 3) << 3;

    // --- load h halo (zero-fill OOB: matches zero-padding semantics) ---
    for (int idx = tid; idx < HSZ * 64; idx += 256) {
        int pos = idx >> 6, c = idx & 63;
        int hn = pos / (HA * HB);
        int rem = pos - hn * (HA * HB);
        int ha = rem / HB, hb = rem - ha * HB;
        int gn = tn - 1 + hn, ga = a0 - 1 + ha, gb = b0 - 1 + hb;
        float v = 0.0f;
        if ((unsigned)gn < 32u && (unsigned)ga < 32u && (unsigned)gb < 32u)
            v = h_in[((gn * 32 + ga) * 32 + gb) * 64 + c];
        h_s[idx] = v;
    }
    // stage Wq into wk_s
    for (int j = tid; j < 1024; j += 256)
        reinterpret_cast<float4*>(wk_s)[j] = reinterpret_cast<const float4*>(Wq)[j];
    __syncthreads();

    // --- per-thread query geometry ---
    int qidx[4], gaq[4], gbq[4];
#pragma unroll
    for (int i = 0; i < 4; i++) {
        int ql = qg * 4 + i;
        int qa = ql >> 3, qb = ql & 7;
        gaq[i] = a0 + qa; gbq[i] = b0 + qb;
        qidx[i] = (HA + (1 + qa)) * HB + (1 + qb);    // center halo index
    }

    // --- q = h @ Wq + bq  (only this thread's 2 channels, 4 queries) ---
    float qx[4], qy[4];
    {
        ull b2 = lds_u64(nullptr) * 0;  // placeholder removed below
        float2 bq2 = *reinterpret_cast<const float2*>(&bq[2 * c2]);
        b2 = pack2(bq2.x, bq2.y);
        ull acc0 = b2, acc1 = b2, acc2 = b2, acc3 = b2;
#pragma unroll 4
        for (int cp = 0; cp < 64; cp++) {
            ull w2 = lds_u64(&wk_s[cp * 64 + 2 * c2]);
            acc0 = ffma2(splat2(h_s[qidx[0] * 64 + cp]), w2, acc0);
            acc1 = ffma2(splat2(h_s[qidx[1] * 64 + cp]), w2, acc1);
            acc2 = ffma2(splat2(h_s[qidx[2] * 64 + cp]), w2, acc2);
            acc3 = ffma2(splat2(h_s[qidx[3] * 64 + cp]), w2, acc3);
        }
        unpack2(acc0, qx[0], qy[0]);
        unpack2(acc1, qx[1], qy[1]);
        unpack2(acc2, qx[2], qy[2]);
        unpack2(acc3, qx[3], qy[3]);
    }

    const float NEG_INF = __int_as_float(0xff800000);
    float mx[4], den[4];
    ull accO[4];
#pragma unroll
    for (int i = 0; i < 4; i++) { mx[i] = NEG_INF; den[i] = 0.0f; accO[i] = 0ull; }

    // --- loop over 27 offsets ---
    for (int m = 0; m < MOFF; m++) {
        __syncthreads();   // protect previous iteration's weight reads
        {
            const float4* wkg = reinterpret_cast<const float4*>(Wk + m * 4096);
            const float4* wvg = reinterpret_cast<const float4*>(Wv + m * 4096);
            for (int j = tid; j < 1024; j += 256) {
                reinterpret_cast<float4*>(wk_s)[j] = wkg[j];
                reinterpret_cast<float4*>(wv_s)[j] = wvg[j];
            }
        }
        __syncthreads();

        int t  = m / 9;
        int r9 = m - t * 9;
        int k1 = r9 / 3, k2 = r9 - k1 * 3;
        int dt = t - 1, di = k1 - 1, dj = k2 - 1;
        int dofs = dt * (HA * HB) + di * HB + dj;

        float2 bk2 = *reinterpret_cast<const float2*>(&bk[m * 64 + 2 * c2]);
        float2 bv2 = *reinterpret_cast<const float2*>(&bv[m * 64 + 2 * c2]);
        ull ak[4], av[4];
        ull bkp = pack2(bk2.x, bk2.y), bvp = pack2(bv2.x, bv2.y);
#pragma unroll
        for (int i = 0; i < 4; i++) { ak[i] = bkp; av[i] = bvp; }

        const float* hbase0 = &h_s[(qidx[0] + dofs) * 64];
        const float* hbase1 = &h_s[(qidx[1] + dofs) * 64];
        const float* hbase2 = &h_s[(qidx[2] + dofs) * 64];
        const float* hbase3 = &h_s[(qidx[3] + dofs) * 64];

#pragma unroll 4
        for (int cp = 0; cp < 64; cp++) {
            ull wkk = lds_u64(&wk_s[cp * 64 + 2 * c2]);
            ull wvv = lds_u64(&wv_s[cp * 64 + 2 * c2]);
            ull h0 = splat2(hbase0[cp]);
            ull h1 = splat2(hbase1[cp]);
            ull h2 = splat2(hbase2[cp]);
            ull h3 = splat2(hbase3[cp]);
            ak[0] = ffma2(h0, wkk, ak[0]);  av[0] = ffma2(h0, wvv, av[0]);
            ak[1] = ffma2(h1, wkk, ak[1]);  av[1] = ffma2(h1, wvv, av[1]);
            ak[2] = ffma2(h2, wkk, ak[2]);  av[2] = ffma2(h2, wvv, av[2]);
            ak[3] = ffma2(h3, wkk, ak[3]);  av[3] = ffma2(h3, wvv, av[3]);
        }

#pragma unroll
        for (int i = 0; i < 4; i++) {
            float kx, ky;
            unpack2(ak[i], kx, ky);
            float s = kx * qx[i] + ky * qy[i];
            // reduce over the 8 lanes of this head (channels 16h..16h+15)
            s += __shfl_xor_sync(0xffffffffu, s, 1);
            s += __shfl_xor_sync(0xffffffffu, s, 2);
            s += __shfl_xor_sync(0xffffffffu, s, 4);
            bool valid = ((unsigned)(gaq[i] + di) < 32u) && ((unsigned)(gbq[i] + dj) < 32u);
            if (!valid) s = -1e30f;          // spatial mask (time is NOT masked)
            float nm    = fmaxf(mx[i], s);
            float scale = __expf(mx[i] - nm);
            float p     = __expf(s - nm);
            mx[i]  = nm;
            den[i] = den[i] * scale + p;
            float ox, oy, vx, vy;
            unpack2(accO[i], ox, oy);
            unpack2(av[i], vx, vy);
            accO[i] = pack2(fmaf(p, vx, ox * scale), fmaf(p, vy, oy * scale));
        }
    }

    // --- epilogue: normalize, add residual, write ---
#pragma unroll
    for (int i = 0; i < 4; i++) {
        float ox, oy;
        unpack2(accO[i], ox, oy);
        float inv = 1.0f / den[i];
        float rx = h_s[qidx[i] * 64 + 2 * c2];
        float ry = h_s[qidx[i] * 64 + 2 * c2 + 1];
        int gpos = (tn * 32 + gaq[i]) * 32 + gbq[i];
        float2 o;
        o.x = ox * inv + rx;
        o.y = oy * inv + ry;
        *reinterpret_cast<float2*>(&h_out[gpos * 64 + 2 * c2]) = o;
    }
}

// ---------------------------------------------------------------------------
// 4) out = h @ W_out + b_out    [NQ, 3]
// ---------------------------------------------------------------------------
__global__ void out_proj_kernel(const float* __restrict__ h,
                                const float* __restrict__ W_out,
                                const float* __restrict__ b_out,
                                float* __restrict__ out) {
    __shared__ float hs[32 * 64];
    int tid = threadIdx.x;              // 128 threads
    int base = blockIdx.x * 32;         // 32 rows per block
    for (int j = tid; j < 2048; j += 128) hs[j] = h[base * 64 + j];
    __syncthreads();
    if (tid < 96) {
        int r = tid / 3, f = tid - 3 * (tid / 3);
        float acc = b_out[f];
#pragma unroll 8
        for (int cp = 0; cp < 64; cp++)
            acc += hs[r * 64 + cp] * W_out[cp * 3 + f];
        out[(base + r) * 3 + f] = acc;
    }
}

// ---------------------------------------------------------------------------
extern "C" void kernel_launch(void* const* d_in, const int* in_sizes, int n_in,
                              void* d_out, int out_size) {
    const float* x     = (const float*)d_in[0];
    const float* W_in  = (const float*)d_in[1];
    const float* b_in  = (const float*)d_in[2];
    const float* W_out = (const float*)d_in[3];
    const float* b_out = (const float*)d_in[4];
    const float* Wq    = (const float*)d_in[5];
    const float* bq    = (const float*)d_in[6];
    const float* Wk    = (const float*)d_in[7];
    const float* bk    = (const float*)d_in[8];
    const float* Wv    = (const float*)d_in[9];
    const float* bv    = (const float*)d_in[10];
    float* out = (float*)d_out;

    float *h0, *h1;
    cudaGetSymbolAddress((void**)&h0, g_h0);
    cudaGetSymbolAddress((void**)&h1, g_h1);
    cudaFuncSetAttribute(attn_kernel, cudaFuncAttributeMaxDynamicSharedMemorySize, ATTN_SMEM);

    bn_stats_kernel<<<1, 1024>>>(x);
    input_proj_kernel<<<(NQ * CH) / 256, 256>>>(x, W_in, b_in, h0);

    // layer 0: h0 -> h1
    attn_kernel<<<1024, 256, ATTN_SMEM>>>(h0, h1,
        Wq + 0 * 4096, bq + 0 * 64,
        Wk + 0 * MOFF * 4096, bk + 0 * MOFF * 64,
        Wv + 0 * MOFF * 4096, bv + 0 * MOFF * 64);
    // layer 1: h1 -> h0
    attn_kernel<<<1024, 256, ATTN_SMEM>>>(h1, h0,
        Wq + 1 * 4096, bq + 1 * 64,
        Wk + 1 * MOFF * 4096, bk + 1 * MOFF * 64,
        Wv + 1 * MOFF * 4096, bv + 1 * MOFF * 64);

    out_proj_kernel<<<NQ / 32, 128>>>(h0, W_out, b_out, out);
}